// round 15
// baseline (speedup 1.0000x reference)
#include <cuda_runtime.h>

// out[n, f, h] = x[n, f] * W[f, h] + b[f, h]
// BATCH=16384, F=128, H=64, fp32. 512 MiB output -> HBM write-stream bound.
//
// R15: R2 skeleton (best, 75.9us), single variable: TPB 256 -> 512.
// Same warp-level instruction stream (1 LDG.32 + 4 FMA + 1 STG.128 .cs per
// row), same total threads/SM; only CTA granularity changes (4096 blocks,
// 32 features per block). Probes scheduling/wave-quantization effects only.
// All other axes closed: N=16 optimal, .cs optimal, 128-bit stores optimal.

#define BATCH 16384
#define NFEAT 128
#define HID   64
#define H4    (HID / 4)               // 16
#define FH    (NFEAT * H4)            // 2048 (f,h4) pairs
#define TPB   512
#define FH_BLOCKS (FH / TPB)          // 4  (32 features per block)
#define N_PER_THREAD 16
#define N_CHUNKS (BATCH / N_PER_THREAD) // 1024

__global__ __launch_bounds__(TPB)
void ifll_kernel(const float* __restrict__ x,
                 const float4* __restrict__ W4,
                 const float4* __restrict__ b4,
                 float4* __restrict__ out)
{
    // blockIdx.x = n_chunk * FH_BLOCKS + f_block
    int fh = (blockIdx.x & (FH_BLOCKS - 1)) * TPB + threadIdx.x; // 0..2047
    int n0 = (blockIdx.x >> 2) * N_PER_THREAD;

    int f = fh >> 4;                  // feature index

    // Per-thread invariant weights: loaded once, amortized over 16 rows.
    float4 w  = __ldg(&W4[fh]);       // W4[f*H4 + h4] == W4[fh]
    float4 bb = __ldg(&b4[fh]);

    const float* xp = x + (size_t)n0 * NFEAT + f;
    float4*      op = out + (size_t)n0 * FH + fh;

    #pragma unroll
    for (int i = 0; i < N_PER_THREAD; i++) {
        float xv = __ldg(xp + i * NFEAT);
        float4 o;
        o.x = fmaf(xv, w.x, bb.x);
        o.y = fmaf(xv, w.y, bb.y);
        o.z = fmaf(xv, w.z, bb.z);
        o.w = fmaf(xv, w.w, bb.w);
        __stcs(op + (size_t)i * FH, o);   // streaming store, evict-first
    }
}

extern "C" void kernel_launch(void* const* d_in, const int* in_sizes, int n_in,
                              void* d_out, int out_size)
{
    const float*  x  = (const float*)d_in[0];
    const float4* W4 = (const float4*)d_in[1];
    const float4* b4 = (const float4*)d_in[2];
    float4* out = (float4*)d_out;

    const int blocks = N_CHUNKS * FH_BLOCKS;  // 4096
    ifll_kernel<<<blocks, TPB>>>(x, W4, b4, out);
}

// round 17
// speedup vs baseline: 1.3679x; 1.3679x over previous
#include <cuda_runtime.h>

// out[n, f, h] = x[n, f] * W[f, h] + b[f, h]
// BATCH=16384, F=128, H=64, fp32. 512 MiB output -> HBM write-stream bound.
//
// FINAL champion (measured 75.9/76.0us across two holds; ~7.2 TB/s effective
// combined BW at natural clocks ~= 90% of 8 TB/s spec):
// - thread owns one (f,h4) pair x 16 batch rows
// - W/b float4 register-resident, amortized 16x
// - per row: 1 broadcast LDG.32 (x) + 4 FMA + 1 STG.128 __stcs
// - warp stores 512 B fully-contiguous segments; evict-first keeps L2 clean
//
// Swept-and-closed axes (single-variable tests):
//   N/thread {1,8,16,32} -> 16   | store width {128b,256b} -> 128b
//   policy {.cs, WB} -> .cs      | TPB {256,512} -> 256
//   x path {LDG, smem} -> tie    | MLP batching -> ptxas already optimal
// Any deviation from {6 CTA/SM x 256thr, N=16, STG.128.cs} trips an L1tex
// replay storm (L1>82%, DRAM<57%) -- observed in R4/R12/R15.

#define BATCH 16384
#define NFEAT 128
#define HID   64
#define H4    (HID / 4)               // 16
#define FH    (NFEAT * H4)            // 2048 (f,h4) pairs
#define TPB   256
#define FH_BLOCKS (FH / TPB)          // 8
#define N_PER_THREAD 16
#define N_CHUNKS (BATCH / N_PER_THREAD) // 1024

__global__ __launch_bounds__(TPB)
void ifll_kernel(const float* __restrict__ x,
                 const float4* __restrict__ W4,
                 const float4* __restrict__ b4,
                 float4* __restrict__ out)
{
    // blockIdx.x = n_chunk * FH_BLOCKS + f_block
    int fh = (blockIdx.x & (FH_BLOCKS - 1)) * TPB + threadIdx.x; // 0..2047
    int n0 = (blockIdx.x >> 3) * N_PER_THREAD;

    int f = fh >> 4;                  // feature index

    // Per-thread invariant weights: loaded once, amortized over 16 rows.
    float4 w  = __ldg(&W4[fh]);       // W4[f*H4 + h4] == W4[fh]
    float4 bb = __ldg(&b4[fh]);

    const float* xp = x + (size_t)n0 * NFEAT + f;
    float4*      op = out + (size_t)n0 * FH + fh;

    #pragma unroll
    for (int i = 0; i < N_PER_THREAD; i++) {
        float xv = __ldg(xp + i * NFEAT);
        float4 o;
        o.x = fmaf(xv, w.x, bb.x);
        o.y = fmaf(xv, w.y, bb.y);
        o.z = fmaf(xv, w.z, bb.z);
        o.w = fmaf(xv, w.w, bb.w);
        __stcs(op + (size_t)i * FH, o);   // streaming store, evict-first
    }
}

extern "C" void kernel_launch(void* const* d_in, const int* in_sizes, int n_in,
                              void* d_out, int out_size)
{
    const float*  x  = (const float*)d_in[0];
    const float4* W4 = (const float4*)d_in[1];
    const float4* b4 = (const float4*)d_in[2];
    float4* out = (float4*)d_out;

    const int blocks = N_CHUNKS * FH_BLOCKS;  // 8192
    ifll_kernel<<<blocks, TPB>>>(x, W4, b4, out);
}